// round 2
// baseline (speedup 1.0000x reference)
#include <cuda_runtime.h>
#include <math.h>

#define N_NODES 6144
#define D_IN    256
#define HID     64
#define OUT_DIM 32
#define ATT_H   128

// ---------------- scratch (device globals; no allocation allowed) ----------
__device__ float g_h0[N_NODES * HID];
__device__ float g_h1[N_NODES * HID];
__device__ float g_m [3 * N_NODES * HID];
__device__ float g_z3[3 * N_NODES * HID];
__device__ float g_s [2 * N_NODES * HID];
__device__ float g_z2[2 * N_NODES * HID];
__device__ float g_relagg [N_NODES * HID];
__device__ float g_itemcls[N_NODES * HID];
__device__ float g_t  [2 * N_NODES * HID];
__device__ float g_zii[2 * N_NODES * HID];
__device__ float g_itemitem[N_NODES * HID];

// ---------------- f32x2 packed helpers (sm_103a) ----------------------------
typedef unsigned long long u64;

__device__ __forceinline__ u64 pk2(float lo, float hi) {
    u64 r;
    asm("mov.b64 %0, {%1, %2};" : "=l"(r)
        : "r"(__float_as_uint(lo)), "r"(__float_as_uint(hi)));
    return r;
}
__device__ __forceinline__ float2 up2(u64 v) {
    unsigned int a, b;
    asm("mov.b64 {%0, %1}, %2;" : "=r"(a), "=r"(b) : "l"(v));
    return make_float2(__uint_as_float(a), __uint_as_float(b));
}
__device__ __forceinline__ void fma2(u64& d, u64 a, u64 b) {
    asm("fma.rn.f32x2 %0, %1, %2, %0;" : "+l"(d) : "l"(a), "l"(b));
}

// ---------------- feature mapping: h = tanh(feat @ W + b) -------------------
// block (64,4): tx = col, ty = row-within-block. grid: N/4
__global__ void __launch_bounds__(256) map_kernel(
    const float* __restrict__ feat, const float* __restrict__ W,
    const float* __restrict__ b, float* __restrict__ out)
{
    int row = blockIdx.x * 4 + threadIdx.y;
    int col = threadIdx.x;
    const float* fr = feat + (size_t)row * D_IN;
    float acc = b[col];
#pragma unroll 8
    for (int k = 0; k < D_IN; k++)
        acc = fmaf(fr[k], W[k * HID + col], acc);
    out[(size_t)row * HID + col] = tanhf(acc);
}

// ---------------- big GEMM: C[b] = A[b] @ H  (N x N) @ (N x 64) -------------
// BM=64 rows, BN=64 (all cols), BK=32. 256 threads, 4x4 micro-tile,
// f32x2 packed FMAs (rows paired).
#define BM 64
#define BK 32

__global__ void __launch_bounds__(256) spmm_kernel(
    const float* __restrict__ A, const float* __restrict__ H,
    float* __restrict__ C)
{
    const float* Ab = A + (size_t)blockIdx.y * N_NODES * N_NODES;
    float*       Cb = C + (size_t)blockIdx.y * N_NODES * HID;

    __shared__ __align__(16) float As[BK][BM + 4];  // transposed A tile
    __shared__ __align__(16) float Hs[BK][HID];

    int tid = threadIdx.x;
    int cg  = tid & 15;   // col group: cols cg*4 .. cg*4+3
    int rg  = tid >> 4;   // row group: rows rg*4 .. rg*4+3
    int row0 = blockIdx.x * BM;

    u64 acc[2][4];
#pragma unroll
    for (int p = 0; p < 2; p++)
#pragma unroll
        for (int c = 0; c < 4; c++) acc[p][c] = 0ULL;

    for (int k0 = 0; k0 < N_NODES; k0 += BK) {
        // load A tile 64x32 (float4), store transposed
#pragma unroll
        for (int i = 0; i < 2; i++) {
            int idx = tid + i * 256;        // 0..511 float4s
            int r   = idx >> 3;             // 0..63
            int c4  = idx & 7;              // 0..7
            float4 v = *(const float4*)(Ab + (size_t)(row0 + r) * N_NODES + k0 + c4 * 4);
            As[c4 * 4 + 0][r] = v.x;
            As[c4 * 4 + 1][r] = v.y;
            As[c4 * 4 + 2][r] = v.z;
            As[c4 * 4 + 3][r] = v.w;
        }
        // load H tile 32x64
#pragma unroll
        for (int i = 0; i < 2; i++) {
            int idx = tid + i * 256;        // 0..511 float4s
            int r   = idx >> 4;             // 0..31
            int c4  = idx & 15;             // 0..15
            *(float4*)&Hs[r][c4 * 4] =
                *(const float4*)(H + (size_t)(k0 + r) * HID + c4 * 4);
        }
        __syncthreads();

#pragma unroll 8
        for (int kk = 0; kk < BK; kk++) {
            float4 av = *(const float4*)&As[kk][rg * 4];
            float4 hv = *(const float4*)&Hs[kk][cg * 4];
            u64 a01 = pk2(av.x, av.y);
            u64 a23 = pk2(av.z, av.w);
            u64 hb0 = pk2(hv.x, hv.x);
            u64 hb1 = pk2(hv.y, hv.y);
            u64 hb2 = pk2(hv.z, hv.z);
            u64 hb3 = pk2(hv.w, hv.w);
            fma2(acc[0][0], a01, hb0);
            fma2(acc[0][1], a01, hb1);
            fma2(acc[0][2], a01, hb2);
            fma2(acc[0][3], a01, hb3);
            fma2(acc[1][0], a23, hb0);
            fma2(acc[1][1], a23, hb1);
            fma2(acc[1][2], a23, hb2);
            fma2(acc[1][3], a23, hb3);
        }
        __syncthreads();
    }

    float2 u00 = up2(acc[0][0]), u01 = up2(acc[0][1]), u02 = up2(acc[0][2]), u03 = up2(acc[0][3]);
    float2 u10 = up2(acc[1][0]), u11 = up2(acc[1][1]), u12 = up2(acc[1][2]), u13 = up2(acc[1][3]);
    int rbase = row0 + rg * 4;
    int cbase = cg * 4;
    *(float4*)&Cb[(size_t)(rbase + 0) * HID + cbase] = make_float4(u00.x, u01.x, u02.x, u03.x);
    *(float4*)&Cb[(size_t)(rbase + 1) * HID + cbase] = make_float4(u00.y, u01.y, u02.y, u03.y);
    *(float4*)&Cb[(size_t)(rbase + 2) * HID + cbase] = make_float4(u10.x, u11.x, u12.x, u13.x);
    *(float4*)&Cb[(size_t)(rbase + 3) * HID + cbase] = make_float4(u10.y, u11.y, u12.y, u13.y);
}

// ---------------- small transform: Z[b] = tanh(X[b] @ W[b] + b[b]) ----------
// X: [batch, N, 64], W stride wStride (0 => shared), b stride bStride.
// block (64,4), grid (N/4, batch)
__global__ void __launch_bounds__(256) relz_kernel(
    const float* __restrict__ X, const float* __restrict__ W,
    const float* __restrict__ bias, float* __restrict__ Z,
    int wStride, int bStride)
{
    int batch = blockIdx.y;
    const float* Xb = X + (size_t)batch * N_NODES * HID;
    const float* Wb = W + (size_t)batch * wStride;
    const float* bb = bias + (size_t)batch * bStride;
    float* Zb = Z + (size_t)batch * N_NODES * HID;

    __shared__ float Ws[HID][HID];
    int tid = threadIdx.y * 64 + threadIdx.x;
    for (int i = tid; i < HID * HID; i += 256)
        Ws[i / HID][i % HID] = Wb[i];
    __syncthreads();

    int row = blockIdx.x * 4 + threadIdx.y;
    int col = threadIdx.x;
    const float* xr = Xb + (size_t)row * HID;
    float acc = bb[col];
#pragma unroll
    for (int k = 0; k < HID; k++)
        acc = fmaf(xr[k], Ws[k][col], acc);
    Zb[(size_t)row * HID + col] = tanhf(acc);
}

// ---------------- attention pooling over K slots ----------------------------
// Z: [K, N, HID]; out[n] = sum_k softmax_k( q . tanh(W z + b) ) * z
// one block (128 threads) per node.
__global__ void __launch_bounds__(128) attn_kernel(
    const float* __restrict__ Z, const float* __restrict__ aW,
    const float* __restrict__ ab, const float* __restrict__ aq,
    float* __restrict__ outp, int K)
{
    int n = blockIdx.x;
    int j = threadIdx.x;   // 0..127 (= ATT_H)
    __shared__ float zs[4 * HID];
    __shared__ float red[ATT_H];
    __shared__ float sc[4];

    for (int k = 0; k < K; k++)
        if (j < HID) zs[k * HID + j] = Z[((size_t)k * N_NODES + n) * HID + j];
    __syncthreads();

    for (int k = 0; k < K; k++) {
        float u = ab[j];
#pragma unroll
        for (int d = 0; d < HID; d++)
            u = fmaf(zs[k * HID + d], aW[d * ATT_H + j], u);
        red[j] = tanhf(u) * aq[j];
        __syncthreads();
#pragma unroll
        for (int off = 64; off >= 1; off >>= 1) {
            if (j < off) red[j] += red[j + off];
            __syncthreads();
        }
        if (j == 0) sc[k] = red[0];
        __syncthreads();
    }

    float mx = -1e30f;
    for (int k = 0; k < K; k++) mx = fmaxf(mx, sc[k]);
    float e[4]; float den = 0.f;
    for (int k = 0; k < K; k++) { e[k] = expf(sc[k] - mx); den += e[k]; }

    if (j < HID) {
        float o = 0.f;
        for (int k = 0; k < K; k++) o += (e[k] / den) * zs[k * HID + j];
        outp[(size_t)n * HID + j] = o;
    }
}

// ---------------- final: attention over {relagg, itemitem}, then project ----
__global__ void __launch_bounds__(128) final_kernel(
    const float* __restrict__ Hrel, const float* __restrict__ Hii,
    const float* __restrict__ aW, const float* __restrict__ ab,
    const float* __restrict__ aq, const float* __restrict__ Wout,
    const float* __restrict__ bout, float* __restrict__ out, int out_total)
{
    int n = blockIdx.x;
    int j = threadIdx.x;
    __shared__ float zs[2 * HID];
    __shared__ float red[ATT_H];
    __shared__ float sc[2];
    __shared__ float pooled[HID];

    if (j < HID) {
        zs[j]       = Hrel[(size_t)n * HID + j];
        zs[HID + j] = Hii [(size_t)n * HID + j];
    }
    __syncthreads();

    for (int k = 0; k < 2; k++) {
        float u = ab[j];
#pragma unroll
        for (int d = 0; d < HID; d++)
            u = fmaf(zs[k * HID + d], aW[d * ATT_H + j], u);
        red[j] = tanhf(u) * aq[j];
        __syncthreads();
#pragma unroll
        for (int off = 64; off >= 1; off >>= 1) {
            if (j < off) red[j] += red[j + off];
            __syncthreads();
        }
        if (j == 0) sc[k] = red[0];
        __syncthreads();
    }

    float mx = fmaxf(sc[0], sc[1]);
    float e0 = expf(sc[0] - mx), e1 = expf(sc[1] - mx);
    float den = e0 + e1;
    float b0 = e0 / den, b1 = e1 / den;

    if (j < HID) pooled[j] = b0 * zs[j] + b1 * zs[HID + j];
    __syncthreads();

    if (j < OUT_DIM) {
        float o = bout[j];
#pragma unroll
        for (int d = 0; d < HID; d++)
            o = fmaf(pooled[d], Wout[d * OUT_DIM + j], o);
        out[(size_t)n * OUT_DIM + j] = o;
    }
    // second output (pooled), if the harness expects it concatenated
    if (out_total > N_NODES * OUT_DIM && j < HID)
        out[(size_t)N_NODES * OUT_DIM + (size_t)n * HID + j] = pooled[j];
}

// ---------------- launch ----------------------------------------------------
extern "C" void kernel_launch(void* const* d_in, const int* in_sizes, int n_in,
                              void* d_out, int out_size)
{
    const float* feat_item = (const float*)d_in[0];
    const float* feat_user = (const float*)d_in[1];
    const float* adj_ii    = (const float*)d_in[2];
    const float* adj_mp    = (const float*)d_in[3];
    const float* adj_ui    = (const float*)d_in[4];
    const float* W_map0 = (const float*)d_in[5];
    const float* b_map0 = (const float*)d_in[6];
    const float* W_map1 = (const float*)d_in[7];
    const float* b_map1 = (const float*)d_in[8];
    const float* W_rel  = (const float*)d_in[9];
    const float* b_rel  = (const float*)d_in[10];
    const float* rel_aW = (const float*)d_in[11];
    const float* rel_ab = (const float*)d_in[12];
    const float* rel_aq = (const float*)d_in[13];
    const float* W_sch  = (const float*)d_in[14];
    const float* b_sch  = (const float*)d_in[15];
    const float* sch_aW = (const float*)d_in[16];
    const float* sch_ab = (const float*)d_in[17];
    const float* sch_aq = (const float*)d_in[18];
    const float* W_ii   = (const float*)d_in[19];
    const float* b_ii   = (const float*)d_in[20];
    const float* ii_aW  = (const float*)d_in[21];
    const float* ii_ab  = (const float*)d_in[22];
    const float* ii_aq  = (const float*)d_in[23];
    const float* fin_aW = (const float*)d_in[24];
    const float* fin_ab = (const float*)d_in[25];
    const float* fin_aq = (const float*)d_in[26];
    const float* W_out  = (const float*)d_in[27];
    const float* b_out  = (const float*)d_in[28];

    float *h0, *h1, *m, *z3, *s, *z2, *relagg, *itemcls, *t, *zii, *itemitem;
    cudaGetSymbolAddress((void**)&h0, g_h0);
    cudaGetSymbolAddress((void**)&h1, g_h1);
    cudaGetSymbolAddress((void**)&m,  g_m);
    cudaGetSymbolAddress((void**)&z3, g_z3);
    cudaGetSymbolAddress((void**)&s,  g_s);
    cudaGetSymbolAddress((void**)&z2, g_z2);
    cudaGetSymbolAddress((void**)&relagg,   g_relagg);
    cudaGetSymbolAddress((void**)&itemcls,  g_itemcls);
    cudaGetSymbolAddress((void**)&t,        g_t);
    cudaGetSymbolAddress((void**)&zii,      g_zii);
    cudaGetSymbolAddress((void**)&itemitem, g_itemitem);

    dim3 blk64x4(64, 4);

    // Stage 1: feature mapping
    map_kernel<<<N_NODES / 4, blk64x4>>>(feat_item, W_map0, b_map0, h0);
    map_kernel<<<N_NODES / 4, blk64x4>>>(feat_user, W_map1, b_map1, h1);

    // Stage 2: big GEMMs phase A
    spmm_kernel<<<dim3(N_NODES / BM, 3), 256>>>(adj_mp, h0, m);
    spmm_kernel<<<dim3(N_NODES / BM, 2), 256>>>(adj_ui, h1, s);

    // Stage 3: per-relation transforms + attention pooling
    relz_kernel<<<dim3(N_NODES / 4, 3), blk64x4>>>(m, W_rel, b_rel, z3, HID * HID, HID);
    relz_kernel<<<dim3(N_NODES / 4, 2), blk64x4>>>(s, W_sch, b_sch, z2, 0, 0);
    attn_kernel<<<N_NODES, 128>>>(z3, rel_aW, rel_ab, rel_aq, relagg, 3);
    attn_kernel<<<N_NODES, 128>>>(z2, sch_aW, sch_ab, sch_aq, itemcls, 2);

    // Stage 4: big GEMMs phase B
    spmm_kernel<<<dim3(N_NODES / BM, 2), 256>>>(adj_ii, itemcls, t);

    // Stage 5: item-item transform + attention
    relz_kernel<<<dim3(N_NODES / 4, 2), blk64x4>>>(t, W_ii, b_ii, zii, HID * HID, HID);
    attn_kernel<<<N_NODES, 128>>>(zii, ii_aW, ii_ab, ii_aq, itemitem, 2);

    // Stage 6: final attention + projection, write outputs
    final_kernel<<<N_NODES, 128>>>(relagg, itemitem, fin_aW, fin_ab, fin_aq,
                                   W_out, b_out, (float*)d_out, out_size);
}

// round 3
// speedup vs baseline: 1.0378x; 1.0378x over previous
#include <cuda_runtime.h>
#include <math.h>

#define N_NODES 6144
#define D_IN    256
#define HID     64
#define OUT_DIM 32
#define ATT_H   128

// ---------------- scratch (device globals; no allocation allowed) ----------
__device__ float g_h0[N_NODES * HID];
__device__ float g_h1[N_NODES * HID];
// split-K partials: up to 15 slabs of [N, HID]
__device__ float g_part[15 * N_NODES * HID];
// reduced GEMM outputs: phase A = [5][N][HID] (m = first 3, s = last 2)
__device__ float g_ms[5 * N_NODES * HID];
__device__ float g_t [2 * N_NODES * HID];
__device__ float g_z3[3 * N_NODES * HID];
__device__ float g_z2[2 * N_NODES * HID];
__device__ float g_zii[2 * N_NODES * HID];
__device__ float g_relagg [N_NODES * HID];
__device__ float g_itemcls[N_NODES * HID];
__device__ float g_itemitem[N_NODES * HID];

// ---------------- f32x2 packed helpers (sm_103a) ----------------------------
typedef unsigned long long u64;

__device__ __forceinline__ u64 pk2(float lo, float hi) {
    u64 r;
    asm("mov.b64 %0, {%1, %2};" : "=l"(r)
        : "r"(__float_as_uint(lo)), "r"(__float_as_uint(hi)));
    return r;
}
__device__ __forceinline__ float2 up2(u64 v) {
    unsigned int a, b;
    asm("mov.b64 {%0, %1}, %2;" : "=r"(a), "=r"(b) : "l"(v));
    return make_float2(__uint_as_float(a), __uint_as_float(b));
}
__device__ __forceinline__ void fma2(u64& d, u64 a, u64 b) {
    asm("fma.rn.f32x2 %0, %1, %2, %0;" : "+l"(d) : "l"(a), "l"(b));
}

// ---------------- feature mapping: h = tanh(feat @ W + b) -------------------
__global__ void __launch_bounds__(256) map_kernel(
    const float* __restrict__ feat, const float* __restrict__ W,
    const float* __restrict__ b, float* __restrict__ out)
{
    int row = blockIdx.x * 4 + threadIdx.y;
    int col = threadIdx.x;
    const float* fr = feat + (size_t)row * D_IN;
    float acc = b[col];
#pragma unroll 8
    for (int k = 0; k < D_IN; k++)
        acc = fmaf(fr[k], W[k * HID + col], acc);
    out[(size_t)row * HID + col] = tanhf(acc);
}

// ---------------- big GEMM with split-K --------------------------------------
// C_part[split][batch] = A[batch][:, kbeg:kend] @ H[kbeg:kend, :]
// BM=128 rows, BN=64 (all cols), BK=32. 256 threads.
// micro-tile: 4 rows x 8 cols per thread, accumulators packed on col pairs.
#define BM 128
#define BK 32

__global__ void __launch_bounds__(256) spmm_kernel(
    const float* __restrict__ adjA, int nA, const float* __restrict__ hA,
    const float* __restrict__ adjB, const float* __restrict__ hB,
    float* __restrict__ part, int kPerSplit)
{
    int b = blockIdx.y;
    const float* A;
    const float* H;
    if (b < nA) { A = adjA + (size_t)b * N_NODES * N_NODES;        H = hA; }
    else        { A = adjB + (size_t)(b - nA) * N_NODES * N_NODES; H = hB; }

    float* Cb = part + ((size_t)blockIdx.z * gridDim.y + b) * N_NODES * HID;

    __shared__ __align__(16) float As[BK][BM + 4];  // transposed A tile
    __shared__ __align__(16) float Hs[BK][HID];

    int tid = threadIdx.x;
    int cg  = tid & 7;    // col group: cols cg*8 .. cg*8+7
    int rg  = tid >> 3;   // row group: rows rg*4 .. rg*4+3
    int row0 = blockIdx.x * BM;
    int kbeg = blockIdx.z * kPerSplit;
    int kend = kbeg + kPerSplit;

    u64 acc[4][4];
#pragma unroll
    for (int r = 0; r < 4; r++)
#pragma unroll
        for (int c = 0; c < 4; c++) acc[r][c] = 0ULL;

    for (int k0 = kbeg; k0 < kend; k0 += BK) {
        // load A tile 128x32, store transposed
#pragma unroll
        for (int i = 0; i < 4; i++) {
            int idx = tid + i * 256;        // 0..1023 float4s
            int r   = idx >> 3;             // 0..127
            int c4  = idx & 7;              // 0..7
            float4 v = *(const float4*)(A + (size_t)(row0 + r) * N_NODES + k0 + c4 * 4);
            As[c4 * 4 + 0][r] = v.x;
            As[c4 * 4 + 1][r] = v.y;
            As[c4 * 4 + 2][r] = v.z;
            As[c4 * 4 + 3][r] = v.w;
        }
        // load H tile 32x64
#pragma unroll
        for (int i = 0; i < 2; i++) {
            int idx = tid + i * 256;        // 0..511 float4s
            int r   = idx >> 4;             // 0..31
            int c4  = idx & 15;             // 0..15
            *(float4*)&Hs[r][c4 * 4] =
                *(const float4*)(H + (size_t)(k0 + r) * HID + c4 * 4);
        }
        __syncthreads();

#pragma unroll
        for (int kk = 0; kk < BK; kk++) {
            float4 av = *(const float4*)&As[kk][rg * 4];
            const u64* hp = (const u64*)&Hs[kk][cg * 8];
            u64 h0 = hp[0], h1 = hp[1], h2 = hp[2], h3 = hp[3];
            u64 a0 = pk2(av.x, av.x);
            u64 a1 = pk2(av.y, av.y);
            u64 a2 = pk2(av.z, av.z);
            u64 a3 = pk2(av.w, av.w);
            fma2(acc[0][0], a0, h0); fma2(acc[0][1], a0, h1);
            fma2(acc[0][2], a0, h2); fma2(acc[0][3], a0, h3);
            fma2(acc[1][0], a1, h0); fma2(acc[1][1], a1, h1);
            fma2(acc[1][2], a1, h2); fma2(acc[1][3], a1, h3);
            fma2(acc[2][0], a2, h0); fma2(acc[2][1], a2, h1);
            fma2(acc[2][2], a2, h2); fma2(acc[2][3], a2, h3);
            fma2(acc[3][0], a3, h0); fma2(acc[3][1], a3, h1);
            fma2(acc[3][2], a3, h2); fma2(acc[3][3], a3, h3);
        }
        __syncthreads();
    }

#pragma unroll
    for (int r = 0; r < 4; r++) {
        float2 p0 = up2(acc[r][0]), p1 = up2(acc[r][1]);
        float2 p2 = up2(acc[r][2]), p3 = up2(acc[r][3]);
        size_t base = (size_t)(row0 + rg * 4 + r) * HID + cg * 8;
        *(float4*)&Cb[base]     = make_float4(p0.x, p0.y, p1.x, p1.y);
        *(float4*)&Cb[base + 4] = make_float4(p2.x, p2.y, p3.x, p3.y);
    }
}

// ---------------- split-K reduce: out[b] = sum_s part[s][b] ------------------
__global__ void __launch_bounds__(256) reduce_kernel(
    const float* __restrict__ part, float* __restrict__ out, int NB, int KS)
{
    const int slab4 = N_NODES * HID / 4;
    int i = blockIdx.x * 256 + threadIdx.x;       // over NB*slab4
    int b = i / slab4;
    int e = i - b * slab4;
    const float4* p4 = (const float4*)part;
    float4 acc = p4[(size_t)b * slab4 + e];
    for (int s = 1; s < KS; s++) {
        float4 v = p4[((size_t)(s * NB + b)) * slab4 + e];
        acc.x += v.x; acc.y += v.y; acc.z += v.z; acc.w += v.w;
    }
    ((float4*)out)[(size_t)b * slab4 + e] = acc;
}

// ---------------- small transform: Z[b] = tanh(X[b] @ W[b] + b[b]) ----------
__global__ void __launch_bounds__(256) relz_kernel(
    const float* __restrict__ X, const float* __restrict__ W,
    const float* __restrict__ bias, float* __restrict__ Z,
    int wStride, int bStride)
{
    int batch = blockIdx.y;
    const float* Xb = X + (size_t)batch * N_NODES * HID;
    const float* Wb = W + (size_t)batch * wStride;
    const float* bb = bias + (size_t)batch * bStride;
    float* Zb = Z + (size_t)batch * N_NODES * HID;

    __shared__ float Ws[HID][HID];
    int tid = threadIdx.y * 64 + threadIdx.x;
    for (int i = tid; i < HID * HID; i += 256)
        Ws[i / HID][i % HID] = Wb[i];
    __syncthreads();

    int row = blockIdx.x * 4 + threadIdx.y;
    int col = threadIdx.x;
    const float* xr = Xb + (size_t)row * HID;
    float acc = bb[col];
#pragma unroll
    for (int k = 0; k < HID; k++)
        acc = fmaf(xr[k], Ws[k][col], acc);
    Zb[(size_t)row * HID + col] = tanhf(acc);
}

// ---------------- attention pooling over K slots ----------------------------
__global__ void __launch_bounds__(128) attn_kernel(
    const float* __restrict__ Z, const float* __restrict__ aW,
    const float* __restrict__ ab, const float* __restrict__ aq,
    float* __restrict__ outp, int K)
{
    int n = blockIdx.x;
    int j = threadIdx.x;
    __shared__ float zs[4 * HID];
    __shared__ float red[ATT_H];
    __shared__ float sc[4];

    for (int k = 0; k < K; k++)
        if (j < HID) zs[k * HID + j] = Z[((size_t)k * N_NODES + n) * HID + j];
    __syncthreads();

    for (int k = 0; k < K; k++) {
        float u = ab[j];
#pragma unroll
        for (int d = 0; d < HID; d++)
            u = fmaf(zs[k * HID + d], aW[d * ATT_H + j], u);
        red[j] = tanhf(u) * aq[j];
        __syncthreads();
#pragma unroll
        for (int off = 64; off >= 1; off >>= 1) {
            if (j < off) red[j] += red[j + off];
            __syncthreads();
        }
        if (j == 0) sc[k] = red[0];
        __syncthreads();
    }

    float mx = -1e30f;
    for (int k = 0; k < K; k++) mx = fmaxf(mx, sc[k]);
    float e[4]; float den = 0.f;
    for (int k = 0; k < K; k++) { e[k] = expf(sc[k] - mx); den += e[k]; }

    if (j < HID) {
        float o = 0.f;
        for (int k = 0; k < K; k++) o += (e[k] / den) * zs[k * HID + j];
        outp[(size_t)n * HID + j] = o;
    }
}

// ---------------- final: attention over {relagg, itemitem}, then project ----
__global__ void __launch_bounds__(128) final_kernel(
    const float* __restrict__ Hrel, const float* __restrict__ Hii,
    const float* __restrict__ aW, const float* __restrict__ ab,
    const float* __restrict__ aq, const float* __restrict__ Wout,
    const float* __restrict__ bout, float* __restrict__ out, int out_total)
{
    int n = blockIdx.x;
    int j = threadIdx.x;
    __shared__ float zs[2 * HID];
    __shared__ float red[ATT_H];
    __shared__ float sc[2];
    __shared__ float pooled[HID];

    if (j < HID) {
        zs[j]       = Hrel[(size_t)n * HID + j];
        zs[HID + j] = Hii [(size_t)n * HID + j];
    }
    __syncthreads();

    for (int k = 0; k < 2; k++) {
        float u = ab[j];
#pragma unroll
        for (int d = 0; d < HID; d++)
            u = fmaf(zs[k * HID + d], aW[d * ATT_H + j], u);
        red[j] = tanhf(u) * aq[j];
        __syncthreads();
#pragma unroll
        for (int off = 64; off >= 1; off >>= 1) {
            if (j < off) red[j] += red[j + off];
            __syncthreads();
        }
        if (j == 0) sc[k] = red[0];
        __syncthreads();
    }

    float mx = fmaxf(sc[0], sc[1]);
    float e0 = expf(sc[0] - mx), e1 = expf(sc[1] - mx);
    float den = e0 + e1;
    float b0 = e0 / den, b1 = e1 / den;

    if (j < HID) pooled[j] = b0 * zs[j] + b1 * zs[HID + j];
    __syncthreads();

    if (j < OUT_DIM) {
        float o = bout[j];
#pragma unroll
        for (int d = 0; d < HID; d++)
            o = fmaf(pooled[d], Wout[d * OUT_DIM + j], o);
        out[(size_t)n * OUT_DIM + j] = o;
    }
    if (out_total > N_NODES * OUT_DIM && j < HID)
        out[(size_t)N_NODES * OUT_DIM + (size_t)n * HID + j] = pooled[j];
}

// ---------------- launch ----------------------------------------------------
extern "C" void kernel_launch(void* const* d_in, const int* in_sizes, int n_in,
                              void* d_out, int out_size)
{
    const float* feat_item = (const float*)d_in[0];
    const float* feat_user = (const float*)d_in[1];
    const float* adj_ii    = (const float*)d_in[2];
    const float* adj_mp    = (const float*)d_in[3];
    const float* adj_ui    = (const float*)d_in[4];
    const float* W_map0 = (const float*)d_in[5];
    const float* b_map0 = (const float*)d_in[6];
    const float* W_map1 = (const float*)d_in[7];
    const float* b_map1 = (const float*)d_in[8];
    const float* W_rel  = (const float*)d_in[9];
    const float* b_rel  = (const float*)d_in[10];
    const float* rel_aW = (const float*)d_in[11];
    const float* rel_ab = (const float*)d_in[12];
    const float* rel_aq = (const float*)d_in[13];
    const float* W_sch  = (const float*)d_in[14];
    const float* b_sch  = (const float*)d_in[15];
    const float* sch_aW = (const float*)d_in[16];
    const float* sch_ab = (const float*)d_in[17];
    const float* sch_aq = (const float*)d_in[18];
    const float* W_ii   = (const float*)d_in[19];
    const float* b_ii   = (const float*)d_in[20];
    const float* ii_aW  = (const float*)d_in[21];
    const float* ii_ab  = (const float*)d_in[22];
    const float* ii_aq  = (const float*)d_in[23];
    const float* fin_aW = (const float*)d_in[24];
    const float* fin_ab = (const float*)d_in[25];
    const float* fin_aq = (const float*)d_in[26];
    const float* W_out  = (const float*)d_in[27];
    const float* b_out  = (const float*)d_in[28];

    float *h0, *h1, *partb, *ms, *t, *z3, *z2, *zii, *relagg, *itemcls, *itemitem;
    cudaGetSymbolAddress((void**)&h0, g_h0);
    cudaGetSymbolAddress((void**)&h1, g_h1);
    cudaGetSymbolAddress((void**)&partb, g_part);
    cudaGetSymbolAddress((void**)&ms, g_ms);
    cudaGetSymbolAddress((void**)&t,  g_t);
    cudaGetSymbolAddress((void**)&z3, g_z3);
    cudaGetSymbolAddress((void**)&z2, g_z2);
    cudaGetSymbolAddress((void**)&zii, g_zii);
    cudaGetSymbolAddress((void**)&relagg,   g_relagg);
    cudaGetSymbolAddress((void**)&itemcls,  g_itemcls);
    cudaGetSymbolAddress((void**)&itemitem, g_itemitem);

    float* m = ms;                              // [3][N][HID]
    float* s = ms + 3 * N_NODES * HID;          // [2][N][HID]

    dim3 blk64x4(64, 4);
    const int slab4 = N_NODES * HID / 4;

    // Stage 1: feature mapping
    map_kernel<<<N_NODES / 4, blk64x4>>>(feat_item, W_map0, b_map0, h0);
    map_kernel<<<N_NODES / 4, blk64x4>>>(feat_user, W_map1, b_map1, h1);

    // Stage 2: phase-A GEMMs, 5 batches (3x adj_mp@h0 + 2x adj_ui@h1), split-K=3
    spmm_kernel<<<dim3(N_NODES / BM, 5, 3), 256>>>(
        adj_mp, 3, h0, adj_ui, h1, partb, N_NODES / 3);
    reduce_kernel<<<5 * slab4 / 256, 256>>>(partb, ms, 5, 3);

    // Stage 3: per-relation transforms + attention pooling
    relz_kernel<<<dim3(N_NODES / 4, 3), blk64x4>>>(m, W_rel, b_rel, z3, HID * HID, HID);
    relz_kernel<<<dim3(N_NODES / 4, 2), blk64x4>>>(s, W_sch, b_sch, z2, 0, 0);
    attn_kernel<<<N_NODES, 128>>>(z3, rel_aW, rel_ab, rel_aq, relagg, 3);
    attn_kernel<<<N_NODES, 128>>>(z2, sch_aW, sch_ab, sch_aq, itemcls, 2);

    // Stage 4: phase-B GEMMs, 2 batches (adj_ii@itemcls), split-K=6
    spmm_kernel<<<dim3(N_NODES / BM, 2, 6), 256>>>(
        adj_ii, 2, itemcls, adj_ii, itemcls, partb, N_NODES / 6);
    reduce_kernel<<<2 * slab4 / 256, 256>>>(partb, t, 2, 6);

    // Stage 5: item-item transform + attention
    relz_kernel<<<dim3(N_NODES / 4, 2), blk64x4>>>(t, W_ii, b_ii, zii, HID * HID, HID);
    attn_kernel<<<N_NODES, 128>>>(zii, ii_aW, ii_ab, ii_aq, itemitem, 2);

    // Stage 6: final attention + projection
    final_kernel<<<N_NODES, 128>>>(relagg, itemitem, fin_aW, fin_ab, fin_aq,
                                   W_out, b_out, (float*)d_out, out_size);
}

// round 4
// speedup vs baseline: 2.2493x; 2.1674x over previous
#include <cuda_runtime.h>
#include <math.h>
#include <stdint.h>

#define N_NODES 6144
#define D_IN    256
#define HID     64
#define OUT_DIM 32
#define ATT_H   128

// ---------------- scratch (device globals; no allocation allowed) ----------
__device__ float g_h0[N_NODES * HID];
__device__ float g_h1[N_NODES * HID];
// split-K partials: up to 10 slabs of [N, HID]
__device__ float g_part[10 * N_NODES * HID];
__device__ float g_z3[3 * N_NODES * HID];
__device__ float g_z2[2 * N_NODES * HID];
__device__ float g_zii[2 * N_NODES * HID];
__device__ float g_relagg [N_NODES * HID];
__device__ float g_itemcls[N_NODES * HID];
__device__ float g_itemitem[N_NODES * HID];

// ---------------- tf32 helpers ----------------------------------------------
__device__ __forceinline__ uint32_t f2tf32(float x) {
    uint32_t u;
    asm("cvt.rna.tf32.f32 %0, %1;" : "=r"(u) : "f"(x));
    return u;
}

__device__ __forceinline__ void mma_tf32(float* c, const uint32_t* a, const uint32_t* b) {
    asm("mma.sync.aligned.m16n8k8.row.col.f32.tf32.tf32.f32 "
        "{%0,%1,%2,%3}, {%4,%5,%6,%7}, {%8,%9}, {%0,%1,%2,%3};"
        : "+f"(c[0]), "+f"(c[1]), "+f"(c[2]), "+f"(c[3])
        : "r"(a[0]), "r"(a[1]), "r"(a[2]), "r"(a[3]),
          "r"(b[0]), "r"(b[1]));
}

// ---------------- feature mapping: h = tanh(feat @ W + b) -------------------
__global__ void __launch_bounds__(256) map_kernel(
    const float* __restrict__ feat, const float* __restrict__ W,
    const float* __restrict__ b, float* __restrict__ out)
{
    int row = blockIdx.x * 4 + threadIdx.y;
    int col = threadIdx.x;
    const float* fr = feat + (size_t)row * D_IN;
    float acc = b[col];
#pragma unroll 8
    for (int k = 0; k < D_IN; k++)
        acc = fmaf(fr[k], W[k * HID + col], acc);
    out[(size_t)row * HID + col] = tanhf(acc);
}

// ---------------- big GEMM, tf32 tensor cores, split-K -----------------------
// C_part[split][batch] = A[batch][:, kbeg:kend] @ H[kbeg:kend, :]
// BM=128 rows, BN=64 (all cols), BK=32. 256 threads = 8 warps (4 M x 2 N),
// each warp computes 32x32 via 2x4 m16n8k8 tf32 mma tiles.
#define BM 128
#define BK 32
#define AS_STRIDE 36   // bank = (g*4 + t) % 32 -> conflict-free A frag loads
#define HS_STRIDE 72   // bank = (t*8 + g) % 32 -> conflict-free B frag loads

__global__ void __launch_bounds__(256) spmm_kernel(
    const float* __restrict__ adjA, int nA, const float* __restrict__ hA,
    const float* __restrict__ adjB, const float* __restrict__ hB,
    float* __restrict__ part, int kPerSplit)
{
    int b = blockIdx.y;
    const float* A;
    const float* H;
    if (b < nA) { A = adjA + (size_t)b * N_NODES * N_NODES;        H = hA; }
    else        { A = adjB + (size_t)(b - nA) * N_NODES * N_NODES; H = hB; }

    float* Cb = part + ((size_t)blockIdx.z * gridDim.y + b) * (size_t)(N_NODES * HID);

    __shared__ uint32_t As[BM * AS_STRIDE];
    __shared__ uint32_t Hs[BK * HS_STRIDE];

    int tid  = threadIdx.x;
    int lane = tid & 31;
    int warp = tid >> 5;
    int g = lane >> 2;     // group id 0..7
    int t = lane & 3;      // thread-in-group 0..3
    int wm = (warp & 3) * 32;   // warp M offset
    int wn = (warp >> 2) * 32;  // warp N offset
    int row0 = blockIdx.x * BM;
    int kbeg = blockIdx.z * kPerSplit;
    int kend = kbeg + kPerSplit;

    float acc[2][4][4];
#pragma unroll
    for (int mt = 0; mt < 2; mt++)
#pragma unroll
        for (int nt = 0; nt < 4; nt++)
#pragma unroll
            for (int i = 0; i < 4; i++) acc[mt][nt][i] = 0.f;

    for (int k0 = kbeg; k0 < kend; k0 += BK) {
        // A tile: 128x32 floats = 1024 float4, 4 per thread; convert to tf32
#pragma unroll
        for (int i = 0; i < 4; i++) {
            int idx = tid + i * 256;
            int r   = idx >> 3;
            int c4  = (idx & 7) << 2;
            float4 v = *(const float4*)(A + (size_t)(row0 + r) * N_NODES + k0 + c4);
            uint4 u;
            u.x = f2tf32(v.x); u.y = f2tf32(v.y);
            u.z = f2tf32(v.z); u.w = f2tf32(v.w);
            *(uint4*)&As[r * AS_STRIDE + c4] = u;
        }
        // H tile: 32x64 floats = 512 float4, 2 per thread
#pragma unroll
        for (int i = 0; i < 2; i++) {
            int idx = tid + i * 256;
            int r   = idx >> 4;
            int c4  = (idx & 15) << 2;
            float4 v = *(const float4*)(H + (size_t)(k0 + r) * HID + c4);
            uint4 u;
            u.x = f2tf32(v.x); u.y = f2tf32(v.y);
            u.z = f2tf32(v.z); u.w = f2tf32(v.w);
            *(uint4*)&Hs[r * HS_STRIDE + c4] = u;
        }
        __syncthreads();

#pragma unroll
        for (int ks = 0; ks < 4; ks++) {
            int kk = ks * 8;
            uint32_t bf[4][2];
#pragma unroll
            for (int nt = 0; nt < 4; nt++) {
                int col = wn + nt * 8 + g;
                bf[nt][0] = Hs[(kk + t)     * HS_STRIDE + col];
                bf[nt][1] = Hs[(kk + t + 4) * HS_STRIDE + col];
            }
#pragma unroll
            for (int mt = 0; mt < 2; mt++) {
                int rbase = wm + mt * 16;
                uint32_t af[4];
                af[0] = As[(rbase + g)     * AS_STRIDE + kk + t];
                af[1] = As[(rbase + g + 8) * AS_STRIDE + kk + t];
                af[2] = As[(rbase + g)     * AS_STRIDE + kk + t + 4];
                af[3] = As[(rbase + g + 8) * AS_STRIDE + kk + t + 4];
#pragma unroll
                for (int nt = 0; nt < 4; nt++)
                    mma_tf32(acc[mt][nt], af, bf[nt]);
            }
        }
        __syncthreads();
    }

    // epilogue: c0,c1 -> (row g, cols 2t,2t+1); c2,c3 -> (row g+8)
#pragma unroll
    for (int mt = 0; mt < 2; mt++) {
        int r_lo = row0 + wm + mt * 16 + g;
#pragma unroll
        for (int nt = 0; nt < 4; nt++) {
            int col = wn + nt * 8 + 2 * t;
            *(float2*)&Cb[(size_t)r_lo * HID + col] =
                make_float2(acc[mt][nt][0], acc[mt][nt][1]);
            *(float2*)&Cb[(size_t)(r_lo + 8) * HID + col] =
                make_float2(acc[mt][nt][2], acc[mt][nt][3]);
        }
    }
}

// ---------------- fused split-K reduce + transform ---------------------------
// Z[by] = tanh( (sum_s part[s][batch0+by]) @ W[by] + bias[by] )
// block (64,4), grid (N/4, nBatches)
__global__ void __launch_bounds__(256) relz_kernel(
    const float* __restrict__ part, int NB, int KS, int batch0,
    const float* __restrict__ W, const float* __restrict__ bias,
    float* __restrict__ Z, int wStride, int bStride)
{
    int batch = batch0 + blockIdx.y;
    const float* Wb = W + (size_t)blockIdx.y * wStride;
    const float* bb = bias + (size_t)blockIdx.y * bStride;
    float* Zb = Z + (size_t)blockIdx.y * N_NODES * HID;

    __shared__ float Ws[HID * HID];
    __shared__ float xs[4][HID];

    int tx = threadIdx.x, ty = threadIdx.y;
    int tid = ty * 64 + tx;
    for (int i = tid; i < HID * HID; i += 256)
        Ws[i] = Wb[i];

    int row = blockIdx.x * 4 + ty;
    const size_t slab = (size_t)N_NODES * HID;
    float v = 0.f;
    for (int s = 0; s < KS; s++)
        v += part[(size_t)(s * NB + batch) * slab + (size_t)row * HID + tx];
    xs[ty][tx] = v;
    __syncthreads();

    float acc = bb[tx];
#pragma unroll
    for (int k = 0; k < HID; k++)
        acc = fmaf(xs[ty][k], Ws[k * HID + tx], acc);
    Zb[(size_t)row * HID + tx] = tanhf(acc);
}

// ---------------- attention pooling over K slots ----------------------------
__global__ void __launch_bounds__(128) attn_kernel(
    const float* __restrict__ Z, const float* __restrict__ aW,
    const float* __restrict__ ab, const float* __restrict__ aq,
    float* __restrict__ outp, int K)
{
    int n = blockIdx.x;
    int j = threadIdx.x;
    __shared__ float zs[4 * HID];
    __shared__ float red[ATT_H];
    __shared__ float sc[4];

    for (int k = 0; k < K; k++)
        if (j < HID) zs[k * HID + j] = Z[((size_t)k * N_NODES + n) * HID + j];
    __syncthreads();

    for (int k = 0; k < K; k++) {
        float u = ab[j];
#pragma unroll
        for (int d = 0; d < HID; d++)
            u = fmaf(zs[k * HID + d], aW[d * ATT_H + j], u);
        red[j] = tanhf(u) * aq[j];
        __syncthreads();
#pragma unroll
        for (int off = 64; off >= 1; off >>= 1) {
            if (j < off) red[j] += red[j + off];
            __syncthreads();
        }
        if (j == 0) sc[k] = red[0];
        __syncthreads();
    }

    float mx = -1e30f;
    for (int k = 0; k < K; k++) mx = fmaxf(mx, sc[k]);
    float e[4]; float den = 0.f;
    for (int k = 0; k < K; k++) { e[k] = expf(sc[k] - mx); den += e[k]; }

    if (j < HID) {
        float o = 0.f;
        for (int k = 0; k < K; k++) o += (e[k] / den) * zs[k * HID + j];
        outp[(size_t)n * HID + j] = o;
    }
}

// ---------------- final: attention over {relagg, itemitem}, then project ----
__global__ void __launch_bounds__(128) final_kernel(
    const float* __restrict__ Hrel, const float* __restrict__ Hii,
    const float* __restrict__ aW, const float* __restrict__ ab,
    const float* __restrict__ aq, const float* __restrict__ Wout,
    const float* __restrict__ bout, float* __restrict__ out, int out_total)
{
    int n = blockIdx.x;
    int j = threadIdx.x;
    __shared__ float zs[2 * HID];
    __shared__ float red[ATT_H];
    __shared__ float sc[2];
    __shared__ float pooled[HID];

    if (j < HID) {
        zs[j]       = Hrel[(size_t)n * HID + j];
        zs[HID + j] = Hii [(size_t)n * HID + j];
    }
    __syncthreads();

    for (int k = 0; k < 2; k++) {
        float u = ab[j];
#pragma unroll
        for (int d = 0; d < HID; d++)
            u = fmaf(zs[k * HID + d], aW[d * ATT_H + j], u);
        red[j] = tanhf(u) * aq[j];
        __syncthreads();
#pragma unroll
        for (int off = 64; off >= 1; off >>= 1) {
            if (j < off) red[j] += red[j + off];
            __syncthreads();
        }
        if (j == 0) sc[k] = red[0];
        __syncthreads();
    }

    float mx = fmaxf(sc[0], sc[1]);
    float e0 = expf(sc[0] - mx), e1 = expf(sc[1] - mx);
    float den = e0 + e1;
    float b0 = e0 / den, b1 = e1 / den;

    if (j < HID) pooled[j] = b0 * zs[j] + b1 * zs[HID + j];
    __syncthreads();

    if (j < OUT_DIM) {
        float o = bout[j];
#pragma unroll
        for (int d = 0; d < HID; d++)
            o = fmaf(pooled[d], Wout[d * OUT_DIM + j], o);
        out[(size_t)n * OUT_DIM + j] = o;
    }
    if (out_total > N_NODES * OUT_DIM && j < HID)
        out[(size_t)N_NODES * OUT_DIM + (size_t)n * HID + j] = pooled[j];
}

// ---------------- launch ----------------------------------------------------
extern "C" void kernel_launch(void* const* d_in, const int* in_sizes, int n_in,
                              void* d_out, int out_size)
{
    const float* feat_item = (const float*)d_in[0];
    const float* feat_user = (const float*)d_in[1];
    const float* adj_ii    = (const float*)d_in[2];
    const float* adj_mp    = (const float*)d_in[3];
    const float* adj_ui    = (const float*)d_in[4];
    const float* W_map0 = (const float*)d_in[5];
    const float* b_map0 = (const float*)d_in[6];
    const float* W_map1 = (const float*)d_in[7];
    const float* b_map1 = (const float*)d_in[8];
    const float* W_rel  = (const float*)d_in[9];
    const float* b_rel  = (const float*)d_in[10];
    const float* rel_aW = (const float*)d_in[11];
    const float* rel_ab = (const float*)d_in[12];
    const float* rel_aq = (const float*)d_in[13];
    const float* W_sch  = (const float*)d_in[14];
    const float* b_sch  = (const float*)d_in[15];
    const float* sch_aW = (const float*)d_in[16];
    const float* sch_ab = (const float*)d_in[17];
    const float* sch_aq = (const float*)d_in[18];
    const float* W_ii   = (const float*)d_in[19];
    const float* b_ii   = (const float*)d_in[20];
    const float* ii_aW  = (const float*)d_in[21];
    const float* ii_ab  = (const float*)d_in[22];
    const float* ii_aq  = (const float*)d_in[23];
    const float* fin_aW = (const float*)d_in[24];
    const float* fin_ab = (const float*)d_in[25];
    const float* fin_aq = (const float*)d_in[26];
    const float* W_out  = (const float*)d_in[27];
    const float* b_out  = (const float*)d_in[28];

    float *h0, *h1, *partb, *z3, *z2, *zii, *relagg, *itemcls, *itemitem;
    cudaGetSymbolAddress((void**)&h0, g_h0);
    cudaGetSymbolAddress((void**)&h1, g_h1);
    cudaGetSymbolAddress((void**)&partb, g_part);
    cudaGetSymbolAddress((void**)&z3, g_z3);
    cudaGetSymbolAddress((void**)&z2, g_z2);
    cudaGetSymbolAddress((void**)&zii, g_zii);
    cudaGetSymbolAddress((void**)&relagg,   g_relagg);
    cudaGetSymbolAddress((void**)&itemcls,  g_itemcls);
    cudaGetSymbolAddress((void**)&itemitem, g_itemitem);

    dim3 blk64x4(64, 4);

    // Stage 1: feature mapping
    map_kernel<<<N_NODES / 4, blk64x4>>>(feat_item, W_map0, b_map0, h0);
    map_kernel<<<N_NODES / 4, blk64x4>>>(feat_user, W_map1, b_map1, h1);

    // Stage 2: phase-A GEMMs (3x adj_mp@h0 + 2x adj_ui@h1), split-K=2
    spmm_kernel<<<dim3(N_NODES / BM, 5, 2), 256>>>(
        adj_mp, 3, h0, adj_ui, h1, partb, N_NODES / 2);

    // Stage 3: fused reduce+transform, then attention pooling
    relz_kernel<<<dim3(N_NODES / 4, 3), blk64x4>>>(
        partb, 5, 2, 0, W_rel, b_rel, z3, HID * HID, HID);
    relz_kernel<<<dim3(N_NODES / 4, 2), blk64x4>>>(
        partb, 5, 2, 3, W_sch, b_sch, z2, 0, 0);
    attn_kernel<<<N_NODES, 128>>>(z3, rel_aW, rel_ab, rel_aq, relagg, 3);
    attn_kernel<<<N_NODES, 128>>>(z2, sch_aW, sch_ab, sch_aq, itemcls, 2);

    // Stage 4: phase-B GEMMs (2x adj_ii@itemcls), split-K=3
    spmm_kernel<<<dim3(N_NODES / BM, 2, 3), 256>>>(
        adj_ii, 2, itemcls, adj_ii, itemcls, partb, N_NODES / 3);

    // Stage 5: fused reduce+transform + attention
    relz_kernel<<<dim3(N_NODES / 4, 2), blk64x4>>>(
        partb, 2, 3, 0, W_ii, b_ii, zii, HID * HID, HID);
    attn_kernel<<<N_NODES, 128>>>(zii, ii_aW, ii_ab, ii_aq, itemitem, 2);

    // Stage 6: final attention + projection
    final_kernel<<<N_NODES, 128>>>(relagg, itemitem, fin_aW, fin_ab, fin_aq,
                                   W_out, b_out, (float*)d_out, out_size);
}

// round 5
// speedup vs baseline: 2.8867x; 1.2834x over previous
#include <cuda_runtime.h>
#include <math.h>
#include <stdint.h>

#define N_NODES 6144
#define D_IN    256
#define HID     64
#define OUT_DIM 32
#define ATT_H   128

// ---------------- scratch (device globals; no allocation allowed) ----------
__device__ float g_h0[N_NODES * HID];
__device__ float g_h1[N_NODES * HID];
__device__ float g_part[10 * N_NODES * HID];
__device__ float g_z3[3 * N_NODES * HID];
__device__ float g_z2[2 * N_NODES * HID];
__device__ float g_zii[2 * N_NODES * HID];
__device__ float g_relagg [N_NODES * HID];
__device__ float g_itemcls[N_NODES * HID];
__device__ float g_itemitem[N_NODES * HID];

// ---------------- tf32 / mma / cp.async helpers ------------------------------
__device__ __forceinline__ uint32_t f2tf32(uint32_t bits) {
    uint32_t u;
    asm("cvt.rna.tf32.f32 %0, %1;" : "=r"(u) : "f"(__uint_as_float(bits)));
    return u;
}

__device__ __forceinline__ void mma_tf32(float* c, const uint32_t* a, const uint32_t* b) {
    asm("mma.sync.aligned.m16n8k8.row.col.f32.tf32.tf32.f32 "
        "{%0,%1,%2,%3}, {%4,%5,%6,%7}, {%8,%9}, {%0,%1,%2,%3};"
        : "+f"(c[0]), "+f"(c[1]), "+f"(c[2]), "+f"(c[3])
        : "r"(a[0]), "r"(a[1]), "r"(a[2]), "r"(a[3]),
          "r"(b[0]), "r"(b[1]));
}

__device__ __forceinline__ void cp16(float* dst, const float* src) {
    uint32_t d = (uint32_t)__cvta_generic_to_shared(dst);
    asm volatile("cp.async.cg.shared.global [%0], [%1], 16;" :: "r"(d), "l"(src));
}
__device__ __forceinline__ void cp_commit() {
    asm volatile("cp.async.commit_group;" ::: "memory");
}
__device__ __forceinline__ void cp_wait2() {
    asm volatile("cp.async.wait_group 2;" ::: "memory");
}

// ---------------- feature mapping: h = tanh(feat @ W + b) -------------------
__global__ void __launch_bounds__(256) map_kernel(
    const float* __restrict__ feat, const float* __restrict__ W,
    const float* __restrict__ b, float* __restrict__ out)
{
    int row = blockIdx.x * 4 + threadIdx.y;
    int col = threadIdx.x;
    const float* fr = feat + (size_t)row * D_IN;
    float acc = b[col];
#pragma unroll 8
    for (int k = 0; k < D_IN; k++)
        acc = fmaf(fr[k], W[k * HID + col], acc);
    out[(size_t)row * HID + col] = tanhf(acc);
}

// ---------------- big GEMM, tf32 mma, 3-stage cp.async pipeline, split-K -----
// BM=128, BN=64, BK=32. 256 threads = 8 warps (4M x 2N), warp tile 32x32.
#define BM 128
#define BK 32
#define AS_STRIDE 36   // floats; 144B (16B-aligned), frag bank = 4g+t (CF)
#define HS_STRIDE 72   // floats; 288B (16B-aligned), frag bank = 8t+g (CF)
#define STAGES 3
#define A_STAGE (BM * AS_STRIDE)
#define H_STAGE (BK * HS_STRIDE)
#define SPMM_SMEM_BYTES (STAGES * (A_STAGE + H_STAGE) * 4)

__device__ __forceinline__ void spmm_load_tile(
    const float* __restrict__ A, const float* __restrict__ H,
    float* as, float* hs, int row0, int k0, int tid)
{
#pragma unroll
    for (int i = 0; i < 4; i++) {
        int idx = tid + i * 256;
        int r   = idx >> 3;
        int c4  = (idx & 7) << 2;
        cp16(as + r * AS_STRIDE + c4, A + (size_t)(row0 + r) * N_NODES + k0 + c4);
    }
#pragma unroll
    for (int i = 0; i < 2; i++) {
        int idx = tid + i * 256;
        int r   = idx >> 4;
        int c4  = (idx & 15) << 2;
        cp16(hs + r * HS_STRIDE + c4, H + (size_t)(k0 + r) * HID + c4);
    }
}

__global__ void __launch_bounds__(256) spmm_kernel(
    const float* __restrict__ adjA, int nA, const float* __restrict__ hA,
    const float* __restrict__ adjB, const float* __restrict__ hB,
    float* __restrict__ part, int kPerSplit)
{
    extern __shared__ float smem[];
    float* AsBase = smem;
    float* HsBase = smem + STAGES * A_STAGE;

    int b = blockIdx.y;
    const float* A;
    const float* H;
    if (b < nA) { A = adjA + (size_t)b * N_NODES * N_NODES;        H = hA; }
    else        { A = adjB + (size_t)(b - nA) * N_NODES * N_NODES; H = hB; }

    float* Cb = part + ((size_t)blockIdx.z * gridDim.y + b) * (size_t)(N_NODES * HID);

    int tid  = threadIdx.x;
    int lane = tid & 31;
    int warp = tid >> 5;
    int g = lane >> 2;
    int t = lane & 3;
    int wm = (warp & 3) * 32;
    int wn = (warp >> 2) * 32;
    int row0 = blockIdx.x * BM;
    int kbeg = blockIdx.z * kPerSplit;
    int nt = kPerSplit / BK;

    float acc[2][4][4];
#pragma unroll
    for (int mt = 0; mt < 2; mt++)
#pragma unroll
        for (int ntl = 0; ntl < 4; ntl++)
#pragma unroll
            for (int i = 0; i < 4; i++) acc[mt][ntl][i] = 0.f;

    // prologue: stages 0..STAGES-2
#pragma unroll
    for (int p = 0; p < STAGES - 1; p++) {
        spmm_load_tile(A, H, AsBase + p * A_STAGE, HsBase + p * H_STAGE,
                       row0, kbeg + p * BK, tid);
        cp_commit();
    }

    for (int i = 0; i < nt; i++) {
        int pre = i + STAGES - 1;
        if (pre < nt) {
            int st = pre % STAGES;
            spmm_load_tile(A, H, AsBase + st * A_STAGE, HsBase + st * H_STAGE,
                           row0, kbeg + pre * BK, tid);
        }
        cp_commit();          // always commit (possibly empty group) -> uniform wait count
        cp_wait2();           // tile i resident
        __syncthreads();

        const uint32_t* as = (const uint32_t*)(AsBase + (i % STAGES) * A_STAGE);
        const uint32_t* hs = (const uint32_t*)(HsBase + (i % STAGES) * H_STAGE);

#pragma unroll
        for (int ks = 0; ks < 4; ks++) {
            int kk = ks * 8;
            uint32_t bf[4][2];
#pragma unroll
            for (int ntl = 0; ntl < 4; ntl++) {
                int col = wn + ntl * 8 + g;
                bf[ntl][0] = f2tf32(hs[(kk + t)     * HS_STRIDE + col]);
                bf[ntl][1] = f2tf32(hs[(kk + t + 4) * HS_STRIDE + col]);
            }
#pragma unroll
            for (int mt = 0; mt < 2; mt++) {
                int rbase = wm + mt * 16;
                uint32_t af[4];
                af[0] = f2tf32(as[(rbase + g)     * AS_STRIDE + kk + t]);
                af[1] = f2tf32(as[(rbase + g + 8) * AS_STRIDE + kk + t]);
                af[2] = f2tf32(as[(rbase + g)     * AS_STRIDE + kk + t + 4]);
                af[3] = f2tf32(as[(rbase + g + 8) * AS_STRIDE + kk + t + 4]);
#pragma unroll
                for (int ntl = 0; ntl < 4; ntl++)
                    mma_tf32(acc[mt][ntl], af, bf[ntl]);
            }
        }
        __syncthreads();
    }

#pragma unroll
    for (int mt = 0; mt < 2; mt++) {
        int r_lo = row0 + wm + mt * 16 + g;
#pragma unroll
        for (int ntl = 0; ntl < 4; ntl++) {
            int col = wn + ntl * 8 + 2 * t;
            *(float2*)&Cb[(size_t)r_lo * HID + col] =
                make_float2(acc[mt][ntl][0], acc[mt][ntl][1]);
            *(float2*)&Cb[(size_t)(r_lo + 8) * HID + col] =
                make_float2(acc[mt][ntl][2], acc[mt][ntl][3]);
        }
    }
}

// ---------------- fused split-K reduce + transform ---------------------------
// Z[by] = tanh( (sum_s part[s][batch0+by]) @ W[by] + bias[by] )
// block (64,4): each thread computes 4 rows x 1 col; 16 rows per block.
__global__ void __launch_bounds__(256) relz_kernel(
    const float* __restrict__ part, int NB, int KS, int batch0,
    const float* __restrict__ W, const float* __restrict__ bias,
    float* __restrict__ Z, int wStride, int bStride)
{
    int batch = batch0 + blockIdx.y;
    const float* Wb = W + (size_t)blockIdx.y * wStride;
    const float* bb = bias + (size_t)blockIdx.y * bStride;
    float* Zb = Z + (size_t)blockIdx.y * N_NODES * HID;

    __shared__ float Ws[HID * HID];
    __shared__ float xs[16][HID];

    int tx = threadIdx.x, ty = threadIdx.y;
    int tid = ty * 64 + tx;
    for (int i = tid; i < HID * HID; i += 256)
        Ws[i] = Wb[i];

    int row0 = blockIdx.x * 16;
    const size_t slab = (size_t)N_NODES * HID;
    // load + reduce 16x64 x-tile
#pragma unroll
    for (int i = 0; i < 4; i++) {
        int idx = tid + i * 256;
        int r = idx >> 6, c = idx & 63;
        float v = 0.f;
        for (int s = 0; s < KS; s++)
            v += part[(size_t)(s * NB + batch) * slab + (size_t)(row0 + r) * HID + c];
        xs[r][c] = v;
    }
    __syncthreads();

    float acc0 = bb[tx], acc1 = acc0, acc2 = acc0, acc3 = acc0;
    int rb = ty * 4;
#pragma unroll
    for (int k = 0; k < HID; k += 4) {
        float w0 = Ws[(k + 0) * HID + tx];
        float w1 = Ws[(k + 1) * HID + tx];
        float w2 = Ws[(k + 2) * HID + tx];
        float w3 = Ws[(k + 3) * HID + tx];
        float4 x0 = *(const float4*)&xs[rb + 0][k];
        float4 x1 = *(const float4*)&xs[rb + 1][k];
        float4 x2 = *(const float4*)&xs[rb + 2][k];
        float4 x3 = *(const float4*)&xs[rb + 3][k];
        acc0 = fmaf(x0.x, w0, fmaf(x0.y, w1, fmaf(x0.z, w2, fmaf(x0.w, w3, acc0))));
        acc1 = fmaf(x1.x, w0, fmaf(x1.y, w1, fmaf(x1.z, w2, fmaf(x1.w, w3, acc1))));
        acc2 = fmaf(x2.x, w0, fmaf(x2.y, w1, fmaf(x2.z, w2, fmaf(x2.w, w3, acc2))));
        acc3 = fmaf(x3.x, w0, fmaf(x3.y, w1, fmaf(x3.z, w2, fmaf(x3.w, w3, acc3))));
    }
    Zb[(size_t)(row0 + rb + 0) * HID + tx] = tanhf(acc0);
    Zb[(size_t)(row0 + rb + 1) * HID + tx] = tanhf(acc1);
    Zb[(size_t)(row0 + rb + 2) * HID + tx] = tanhf(acc2);
    Zb[(size_t)(row0 + rb + 3) * HID + tx] = tanhf(acc3);
}

// ---------------- attention pooling over K slots ----------------------------
__global__ void __launch_bounds__(128) attn_kernel(
    const float* __restrict__ Z, const float* __restrict__ aW,
    const float* __restrict__ ab, const float* __restrict__ aq,
    float* __restrict__ outp, int K)
{
    int n = blockIdx.x;
    int j = threadIdx.x;
    __shared__ float zs[4 * HID];
    __shared__ float red[ATT_H];
    __shared__ float sc[4];

    for (int k = 0; k < K; k++)
        if (j < HID) zs[k * HID + j] = Z[((size_t)k * N_NODES + n) * HID + j];
    __syncthreads();

    for (int k = 0; k < K; k++) {
        float u = ab[j];
#pragma unroll
        for (int d = 0; d < HID; d++)
            u = fmaf(zs[k * HID + d], aW[d * ATT_H + j], u);
        red[j] = tanhf(u) * aq[j];
        __syncthreads();
#pragma unroll
        for (int off = 64; off >= 1; off >>= 1) {
            if (j < off) red[j] += red[j + off];
            __syncthreads();
        }
        if (j == 0) sc[k] = red[0];
        __syncthreads();
    }

    float mx = -1e30f;
    for (int k = 0; k < K; k++) mx = fmaxf(mx, sc[k]);
    float e[4]; float den = 0.f;
    for (int k = 0; k < K; k++) { e[k] = expf(sc[k] - mx); den += e[k]; }

    if (j < HID) {
        float o = 0.f;
        for (int k = 0; k < K; k++) o += (e[k] / den) * zs[k * HID + j];
        outp[(size_t)n * HID + j] = o;
    }
}

// ---------------- final: attention over {relagg, itemitem}, then project ----
__global__ void __launch_bounds__(128) final_kernel(
    const float* __restrict__ Hrel, const float* __restrict__ Hii,
    const float* __restrict__ aW, const float* __restrict__ ab,
    const float* __restrict__ aq, const float* __restrict__ Wout,
    const float* __restrict__ bout, float* __restrict__ out, int out_total)
{
    int n = blockIdx.x;
    int j = threadIdx.x;
    __shared__ float zs[2 * HID];
    __shared__ float red[ATT_H];
    __shared__ float sc[2];
    __shared__ float pooled[HID];

    if (j < HID) {
        zs[j]       = Hrel[(size_t)n * HID + j];
        zs[HID + j] = Hii [(size_t)n * HID + j];
    }
    __syncthreads();

    for (int k = 0; k < 2; k++) {
        float u = ab[j];
#pragma unroll
        for (int d = 0; d < HID; d++)
            u = fmaf(zs[k * HID + d], aW[d * ATT_H + j], u);
        red[j] = tanhf(u) * aq[j];
        __syncthreads();
#pragma unroll
        for (int off = 64; off >= 1; off >>= 1) {
            if (j < off) red[j] += red[j + off];
            __syncthreads();
        }
        if (j == 0) sc[k] = red[0];
        __syncthreads();
    }

    float mx = fmaxf(sc[0], sc[1]);
    float e0 = expf(sc[0] - mx), e1 = expf(sc[1] - mx);
    float den = e0 + e1;
    float b0 = e0 / den, b1 = e1 / den;

    if (j < HID) pooled[j] = b0 * zs[j] + b1 * zs[HID + j];
    __syncthreads();

    if (j < OUT_DIM) {
        float o = bout[j];
#pragma unroll
        for (int d = 0; d < HID; d++)
            o = fmaf(pooled[d], Wout[d * OUT_DIM + j], o);
        out[(size_t)n * OUT_DIM + j] = o;
    }
    if (out_total > N_NODES * OUT_DIM && j < HID)
        out[(size_t)N_NODES * OUT_DIM + (size_t)n * HID + j] = pooled[j];
}

// ---------------- launch ----------------------------------------------------
extern "C" void kernel_launch(void* const* d_in, const int* in_sizes, int n_in,
                              void* d_out, int out_size)
{
    const float* feat_item = (const float*)d_in[0];
    const float* feat_user = (const float*)d_in[1];
    const float* adj_ii    = (const float*)d_in[2];
    const float* adj_mp    = (const float*)d_in[3];
    const float* adj_ui    = (const float*)d_in[4];
    const float* W_map0 = (const float*)d_in[5];
    const float* b_map0 = (const float*)d_in[6];
    const float* W_map1 = (const float*)d_in[7];
    const float* b_map1 = (const float*)d_in[8];
    const float* W_rel  = (const float*)d_in[9];
    const float* b_rel  = (const float*)d_in[10];
    const float* rel_aW = (const float*)d_in[11];
    const float* rel_ab = (const float*)d_in[12];
    const float* rel_aq = (const float*)d_in[13];
    const float* W_sch  = (const float*)d_in[14];
    const float* b_sch  = (const float*)d_in[15];
    const float* sch_aW = (const float*)d_in[16];
    const float* sch_ab = (const float*)d_in[17];
    const float* sch_aq = (const float*)d_in[18];
    const float* W_ii   = (const float*)d_in[19];
    const float* b_ii   = (const float*)d_in[20];
    const float* ii_aW  = (const float*)d_in[21];
    const float* ii_ab  = (const float*)d_in[22];
    const float* ii_aq  = (const float*)d_in[23];
    const float* fin_aW = (const float*)d_in[24];
    const float* fin_ab = (const float*)d_in[25];
    const float* fin_aq = (const float*)d_in[26];
    const float* W_out  = (const float*)d_in[27];
    const float* b_out  = (const float*)d_in[28];

    float *h0, *h1, *partb, *z3, *z2, *zii, *relagg, *itemcls, *itemitem;
    cudaGetSymbolAddress((void**)&h0, g_h0);
    cudaGetSymbolAddress((void**)&h1, g_h1);
    cudaGetSymbolAddress((void**)&partb, g_part);
    cudaGetSymbolAddress((void**)&z3, g_z3);
    cudaGetSymbolAddress((void**)&z2, g_z2);
    cudaGetSymbolAddress((void**)&zii, g_zii);
    cudaGetSymbolAddress((void**)&relagg,   g_relagg);
    cudaGetSymbolAddress((void**)&itemcls,  g_itemcls);
    cudaGetSymbolAddress((void**)&itemitem, g_itemitem);

    cudaFuncSetAttribute(spmm_kernel,
                         cudaFuncAttributeMaxDynamicSharedMemorySize,
                         SPMM_SMEM_BYTES);

    dim3 blk64x4(64, 4);

    // Stage 1: feature mapping
    map_kernel<<<N_NODES / 4, blk64x4>>>(feat_item, W_map0, b_map0, h0);
    map_kernel<<<N_NODES / 4, blk64x4>>>(feat_user, W_map1, b_map1, h1);

    // Stage 2: phase-A GEMMs (3x adj_mp@h0 + 2x adj_ui@h1), split-K=2
    spmm_kernel<<<dim3(N_NODES / BM, 5, 2), 256, SPMM_SMEM_BYTES>>>(
        adj_mp, 3, h0, adj_ui, h1, partb, N_NODES / 2);

    // Stage 3: fused reduce+transform, then attention pooling
    relz_kernel<<<dim3(N_NODES / 16, 3), blk64x4>>>(
        partb, 5, 2, 0, W_rel, b_rel, z3, HID * HID, HID);
    relz_kernel<<<dim3(N_NODES / 16, 2), blk64x4>>>(
        partb, 5, 2, 3, W_sch, b_sch, z2, 0, 0);
    attn_kernel<<<N_NODES, 128>>>(z3, rel_aW, rel_ab, rel_aq, relagg, 3);
    attn_kernel<<<N_NODES, 128>>>(z2, sch_aW, sch_ab, sch_aq, itemcls, 2);

    // Stage 4: phase-B GEMMs (2x adj_ii@itemcls), split-K=3
    spmm_kernel<<<dim3(N_NODES / BM, 2, 3), 256, SPMM_SMEM_BYTES>>>(
        adj_ii, 2, itemcls, adj_ii, itemcls, partb, N_NODES / 3);

    // Stage 5: fused reduce+transform + attention
    relz_kernel<<<dim3(N_NODES / 16, 2), blk64x4>>>(
        partb, 2, 3, 0, W_ii, b_ii, zii, HID * HID, HID);
    attn_kernel<<<N_NODES, 128>>>(zii, ii_aW, ii_ab, ii_aq, itemitem, 2);

    // Stage 6: final attention + projection
    final_kernel<<<N_NODES, 128>>>(relagg, itemitem, fin_aW, fin_ab, fin_aq,
                                   W_out, b_out, (float*)d_out, out_size);
}